// round 8
// baseline (speedup 1.0000x reference)
#include <cuda_runtime.h>
#include <cuda_fp16.h>
#include <cstdint>

#define T  4096
#define D  1024
#define H  16
#define HS 64

// fp16 scratch
__device__ __half g_K [(size_t)H * T * HS];    // "queries" (reference swaps roles)
__device__ __half g_Q [(size_t)H * T * HS];    // "keys"
__device__ __half g_V [(size_t)H * T * HS];    // values (natural layout)
__device__ __half g_Wt[(size_t)3 * H * HS * D];// weights transposed: [which][h][s][d]
__device__ __half g_xc[(size_t)T * D];         // x, fp16

// ---------------------------------------------------------------------------
__device__ __forceinline__ uint32_t smem_u32(const void* p) {
    uint32_t a;
    asm("{ .reg .u64 t; cvta.to.shared.u64 t, %1; cvt.u32.u64 %0, t; }" : "=r"(a) : "l"(p));
    return a;
}
__device__ __forceinline__ float ex2f(float x) {
    float r;
    asm("ex2.approx.f32 %0, %1;" : "=f"(r) : "f"(x));
    return r;
}
__device__ __forceinline__ void ldmx4(uint32_t r[4], uint32_t a) {
    asm volatile("ldmatrix.sync.aligned.m8n8.x4.shared.b16 {%0,%1,%2,%3}, [%4];"
                 : "=r"(r[0]), "=r"(r[1]), "=r"(r[2]), "=r"(r[3]) : "r"(a));
}
__device__ __forceinline__ void ldmx4t(uint32_t r[4], uint32_t a) {
    asm volatile("ldmatrix.sync.aligned.m8n8.x4.trans.shared.b16 {%0,%1,%2,%3}, [%4];"
                 : "=r"(r[0]), "=r"(r[1]), "=r"(r[2]), "=r"(r[3]) : "r"(a));
}
__device__ __forceinline__ void mma16(float d[4], const uint32_t a[4],
                                      uint32_t b0, uint32_t b1) {
    asm volatile("mma.sync.aligned.m16n8k16.row.col.f32.f16.f16.f32 "
                 "{%0,%1,%2,%3}, {%4,%5,%6,%7}, {%8,%9}, {%0,%1,%2,%3};"
                 : "+f"(d[0]), "+f"(d[1]), "+f"(d[2]), "+f"(d[3])
                 : "r"(a[0]), "r"(a[1]), "r"(a[2]), "r"(a[3]), "r"(b0), "r"(b1));
}
__device__ __forceinline__ uint32_t packh2(float lo, float hi) {
    __half2 h = __floats2half2_rn(lo, hi);
    return *(uint32_t*)&h;
}
#define CPA16(dst, src) asm volatile("cp.async.cg.shared.global [%0], [%1], 16;" :: "r"(dst), "l"(src) : "memory")
#define CPC()  asm volatile("cp.async.commit_group;" ::: "memory")
#define CPW0() asm volatile("cp.async.wait_group 0;" ::: "memory")

// rows of 64 halfs (128 B = 8x16B units); XOR-swizzle -> conflict-free ldmatrix
__device__ __forceinline__ uint32_t swb(uint32_t row, uint32_t u) {
    return row * 128u + ((u ^ (row & 7u)) << 4);
}

// ---------------------------------------------------------------------------
__global__ __launch_bounds__(256) void xconv(const float* __restrict__ x) {
    int i = blockIdx.x * 256 + threadIdx.x;     // float4 index
    float4 v = ((const float4*)x)[i];
    __half2 a = __floats2half2_rn(v.x, v.y), b = __floats2half2_rn(v.z, v.w);
    *(__half2*)(g_xc + i * 4)     = a;
    *(__half2*)(g_xc + i * 4 + 2) = b;
}

__global__ void wtrans(const float* __restrict__ Wk, const float* __restrict__ Wq,
                       const float* __restrict__ Wv) {
    const int which = blockIdx.z / H, h = blockIdx.z % H;
    const float* W = ((which == 0) ? Wk : (which == 1) ? Wq : Wv) + (size_t)h * D * HS;
    const int d0 = blockIdx.x * 32, s0 = blockIdx.y * 32;
    __shared__ float t[32][33];
    const int tx = threadIdx.x, ty = threadIdx.y;
    #pragma unroll
    for (int i = 0; i < 4; i++)
        t[ty + i * 8][tx] = W[(size_t)(d0 + ty + i * 8) * HS + s0 + tx];
    __syncthreads();
    __half* o = g_Wt + ((size_t)(which * H + h) * HS + s0) * D + d0;
    #pragma unroll
    for (int i = 0; i < 4; i++)
        o[(size_t)(ty + i * 8) * D + tx] = __float2half_rn(t[tx][ty + i * 8]);
}

// ---------------------------------------------------------------------------
// Projection: Out[h][t][s] = sum_d xc[t][d] * Wt[wh][h][s][d]   (fp16 HMMA)
// M=128, N=64, K chunks of 64, 2-stage cp.async, one barrier per chunk.
// SMEM: A 2x(128x64 h), B 2x(64x64 h) = 49152 B.
// ---------------------------------------------------------------------------
__global__ __launch_bounds__(128, 3) void proj_tc() {
    extern __shared__ char smc[];
    const int tid = threadIdx.x, w = tid >> 5, l = tid & 31;
    const int mt = blockIdx.x, h = blockIdx.y, wh = blockIdx.z;
    const __half* A = g_xc + (size_t)mt * 128 * D;
    const __half* B = g_Wt + (size_t)(wh * H + h) * HS * D;
    const uint32_t sA = smem_u32(smc);            // 2 x 16384
    const uint32_t sB = sA + 2 * 16384;           // 2 x 8192

    auto stage = [&](int c, int st) {
        const __half* ap = A + c * 64;
        uint32_t da = sA + st * 16384;
        #pragma unroll
        for (int i = 0; i < 8; i++) {
            int id = tid + i * 128, r = id >> 3, u = id & 7;
            CPA16(da + swb(r, u), ap + (size_t)r * D + u * 8);
        }
        const __half* bp = B + c * 64;
        uint32_t db = sB + st * 8192;
        #pragma unroll
        for (int i = 0; i < 4; i++) {
            int id = tid + i * 128, r = id >> 3, u = id & 7;
            CPA16(db + swb(r, u), bp + (size_t)r * D + u * 8);
        }
    };
    stage(0, 0); CPC();

    float acc[2][8][4] = {};
    const int ar = ((l >> 3) & 1) * 8 + (l & 7);
    const int au = (l >> 4) & 1;
    const int kr = (l >> 4) * 8 + (l & 7);        // B-frag row pattern
    const int ku = (l >> 3) & 1;

    for (int c = 0; c < 16; c++) {
        const int st = c & 1;
        CPW0();
        __syncthreads();
        if (c + 1 < 16) { stage(c + 1, st ^ 1); CPC(); }
        const uint32_t abase = sA + st * 16384 + (w * 32) * 128;
        const uint32_t bbase = sB + st * 8192;
        #pragma unroll
        for (int kb = 0; kb < 4; kb++) {
            uint32_t qa0[4], qa1[4];
            ldmx4(qa0, abase + swb(ar,      2 * kb + au));
            ldmx4(qa1, abase + swb(16 + ar, 2 * kb + au));
            #pragma unroll
            for (int np = 0; np < 4; np++) {
                uint32_t q[4];
                ldmx4(q, bbase + swb(16 * np + kr, 2 * kb + ku));
                mma16(acc[0][2 * np],     qa0, q[0], q[1]);
                mma16(acc[0][2 * np + 1], qa0, q[2], q[3]);
                mma16(acc[1][2 * np],     qa1, q[0], q[1]);
                mma16(acc[1][2 * np + 1], qa1, q[2], q[3]);
            }
        }
    }

    __half* o = ((wh == 0) ? g_K : (wh == 1) ? g_Q : g_V) + (size_t)h * T * HS;
    #pragma unroll
    for (int mi = 0; mi < 2; mi++)
        #pragma unroll
        for (int ns = 0; ns < 8; ns++) {
            int s = ns * 8 + 2 * (l & 3);
            int t = mt * 128 + w * 32 + mi * 16 + (l >> 2);
            *(uint32_t*)(o + (size_t)t * HS + s)       = packh2(acc[mi][ns][0], acc[mi][ns][1]);
            *(uint32_t*)(o + (size_t)(t + 8) * HS + s) = packh2(acc[mi][ns][2], acc[mi][ns][3]);
        }
}

// ---------------------------------------------------------------------------
// Fused causal attention, fp16 HMMA. CTA = (q-tile pair, head), 128 threads.
// 64-row q-tiles; CTA processes tiles {pair, 63-pair} -> uniform 65 kv-blocks.
// Inner loop software-pipelined: S-mma of column-block ntp+1 issued before
// softmax+O-mma of block ntp (tensor overlaps MUFU/FMA).
// SMEM 32 KB: K[2][64x64h] @0, V[2][64x64h] @16384. Q staged through K region.
// ---------------------------------------------------------------------------
__global__ __launch_bounds__(128, 4) void attn_tc(float* __restrict__ out) {
    extern __shared__ char smc[];
    const uint32_t sb = smem_u32(smc);
    const int tid = threadIdx.x, w = tid >> 5, l = tid & 31;
    const int pair = blockIdx.x, h = blockIdx.y;

    const __half* Qh = g_K + (size_t)h * T * HS;   // acts as queries
    const __half* Kp = g_Q + (size_t)h * T * HS;   // acts as keys
    const __half* Vp = g_V + (size_t)h * T * HS;

    const int ar = ((l >> 3) & 1) * 8 + (l & 7);
    const int au = (l >> 4) & 1;
    const int kr = (l >> 4) * 8 + (l & 7);        // K B-frag rows
    const int ku = (l >> 3) & 1;
    const int vr = ((l >> 3) & 1) * 8 + (l & 7);  // V trans-frag rows
    const int vu = (l >> 4) & 1;
    const int qd = l & 3, rlo = l >> 2;
    const float C = 0.18033688f;                  // 0.125 * log2(e)

    auto stage = [&](int kbp, int stg) {
        const __half* kp = Kp + (size_t)kbp * 64 * HS;
        const uint32_t kd = sb + stg * 8192;
        #pragma unroll
        for (int i = 0; i < 4; i++) {
            int id = tid + i * 128, r = id >> 3, u = id & 7;
            CPA16(kd + swb(r, u), kp + (size_t)r * HS + u * 8);
        }
        const __half* vp = Vp + (size_t)kbp * 64 * HS;
        const uint32_t vd = sb + 16384 + stg * 8192;
        #pragma unroll
        for (int i = 0; i < 4; i++) {
            int id = tid + i * 128, r = id >> 3, u = id & 7;
            CPA16(vd + swb(r, u), vp + (size_t)r * HS + u * 8);
        }
    };

    #pragma unroll 1
    for (int tile = 0; tile < 2; tile++) {
        const int qb  = tile ? (63 - pair) : pair;
        const int nkb = qb + 1;
        const int row0 = qb * 64 + w * 16;

        // drain any in-flight prefetch from previous tile, then stage Q
        CPW0();
        __syncthreads();
        const __half* Qp = Qh + (size_t)qb * 64 * HS;
        #pragma unroll
        for (int i = 0; i < 4; i++) {
            int id = tid + i * 128, r = id >> 3, u = id & 7;
            CPA16(sb + swb(r, u), Qp + (size_t)r * HS + u * 8);
        }
        CPC(); CPW0();
        __syncthreads();
        uint32_t qa[4][4];
        #pragma unroll
        for (int kb2 = 0; kb2 < 4; kb2++)
            ldmx4(qa[kb2], sb + swb(w * 16 + ar, 2 * kb2 + au));
        __syncthreads();

        stage(0, 0); CPC();

        float oacc[8][4] = {};
        float ls[2] = {};

        for (int kb = 0; kb < nkb; kb++) {
            const int st = kb & 1;
            CPW0();
            __syncthreads();
            const int kbp = (kb + 1 < nkb) ? kb + 1 : kb;
            stage(kbp, st ^ 1); CPC();

            const uint32_t kbase = sb + st * 8192;
            const uint32_t vbase = sb + 16384 + st * 8192;
            const int cb0 = kb * 64;

            // number of live 16-column blocks for this warp (1..4)
            int lim = ((row0 + 15 - cb0) >> 4) + 1;
            if (lim > 4) lim = 4;

            // --- S-mma for column block ntp into sacc ---
            auto smma = [&](int ntp, float sacc[2][4]) {
                sacc[0][0] = sacc[0][1] = sacc[0][2] = sacc[0][3] = 0.0f;
                sacc[1][0] = sacc[1][1] = sacc[1][2] = sacc[1][3] = 0.0f;
                #pragma unroll
                for (int kb2 = 0; kb2 < 4; kb2++) {
                    uint32_t q[4];
                    ldmx4(q, kbase + swb(16 * ntp + kr, 2 * kb2 + ku));
                    mma16(sacc[0], qa[kb2], q[0], q[1]);
                    mma16(sacc[1], qa[kb2], q[2], q[3]);
                }
            };
            // --- softmax + O-mma for column block ntp ---
            auto proc = [&](int ntp, float sacc[2][4]) {
                const int cmin = cb0 + ntp * 16;
                const bool nomask = (cmin + 15) <= row0;
                float e[2][4];
                #pragma unroll
                for (int ni = 0; ni < 2; ni++) {
                    if (nomask) {
                        e[ni][0] = ex2f(sacc[ni][0] * C);
                        e[ni][1] = ex2f(sacc[ni][1] * C);
                        e[ni][2] = ex2f(sacc[ni][2] * C);
                        e[ni][3] = ex2f(sacc[ni][3] * C);
                    } else {
                        const int c0 = cmin + ni * 8 + 2 * qd;
                        const int r0 = row0 + rlo;
                        e[ni][0] = (c0     <= r0    ) ? ex2f(sacc[ni][0] * C) : 0.0f;
                        e[ni][1] = (c0 + 1 <= r0    ) ? ex2f(sacc[ni][1] * C) : 0.0f;
                        e[ni][2] = (c0     <= r0 + 8) ? ex2f(sacc[ni][2] * C) : 0.0f;
                        e[ni][3] = (c0 + 1 <= r0 + 8) ? ex2f(sacc[ni][3] * C) : 0.0f;
                    }
                    ls[0] += e[ni][0] + e[ni][1];
                    ls[1] += e[ni][2] + e[ni][3];
                }
                uint32_t pa[4];
                pa[0] = packh2(e[0][0], e[0][1]);
                pa[1] = packh2(e[0][2], e[0][3]);
                pa[2] = packh2(e[1][0], e[1][1]);
                pa[3] = packh2(e[1][2], e[1][3]);
                #pragma unroll
                for (int jp = 0; jp < 4; jp++) {
                    uint32_t q[4];
                    ldmx4t(q, vbase + swb(16 * ntp + vr, 2 * jp + vu));
                    mma16(oacc[2 * jp],     pa, q[0], q[1]);
                    mma16(oacc[2 * jp + 1], pa, q[2], q[3]);
                }
            };

            // explicit depth-1 lookahead ladder (ping-pong sacc buffers)
            float sa[2][4], sbuf[2][4];
            smma(0, sa);
            if (lim > 1) {
                smma(1, sbuf);
                proc(0, sa);
                if (lim > 2) {
                    smma(2, sa);
                    proc(1, sbuf);
                    if (lim > 3) {
                        smma(3, sbuf);
                        proc(2, sa);
                        proc(3, sbuf);
                    } else {
                        proc(2, sa);
                    }
                } else {
                    proc(1, sbuf);
                }
            } else {
                proc(0, sa);
            }
        }

        // finalize tile: quad-reduce row sums, scale, store
        #pragma unroll
        for (int hf = 0; hf < 2; hf++) {
            float v = ls[hf];
            v += __shfl_xor_sync(0xffffffffu, v, 1);
            v += __shfl_xor_sync(0xffffffffu, v, 2);
            ls[hf] = 1.0f / v;
        }
        #pragma unroll
        for (int ns = 0; ns < 8; ns++) {
            int t0 = row0 + rlo;
            int c  = h * HS + ns * 8 + 2 * qd;
            *(float2*)(out + (size_t)t0 * (H * HS) + c) =
                make_float2(oacc[ns][0] * ls[0], oacc[ns][1] * ls[0]);
            *(float2*)(out + (size_t)(t0 + 8) * (H * HS) + c) =
                make_float2(oacc[ns][2] * ls[1], oacc[ns][3] * ls[1]);
        }
    }
}

// ---------------------------------------------------------------------------
extern "C" void kernel_launch(void* const* d_in, const int* in_sizes, int n_in,
                              void* d_out, int out_size) {
    const float* x  = (const float*)d_in[0];
    const float* Wk = (const float*)d_in[1];
    const float* Wq = (const float*)d_in[2];
    const float* Wv = (const float*)d_in[3];
    float* out = (float*)d_out;

    cudaFuncSetAttribute(proj_tc, cudaFuncAttributeMaxDynamicSharedMemorySize, 49152);
    cudaFuncSetAttribute(attn_tc, cudaFuncAttributeMaxDynamicSharedMemorySize, 32768);

    xconv<<<T * D / 4 / 256, 256>>>(x);
    wtrans<<<dim3(D / 32, HS / 32, 3 * H), dim3(32, 8)>>>(Wk, Wq, Wv);
    proj_tc<<<dim3(T / 128, H, 3), 128, 49152>>>();
    attn_tc<<<dim3(T / 128 * 2 / 2, H), 128, 32768>>>(out);
}

// round 9
// speedup vs baseline: 1.0271x; 1.0271x over previous
#include <cuda_runtime.h>
#include <cuda_fp16.h>
#include <cstdint>

#define T  4096
#define D  1024
#define H  16
#define HS 64

// fp16 scratch
__device__ __half g_K [(size_t)H * T * HS];    // "queries" (reference swaps roles)
__device__ __half g_Q [(size_t)H * T * HS];    // "keys"
__device__ __half g_V [(size_t)H * T * HS];    // values (natural layout)
__device__ __half g_Wt[(size_t)3 * H * HS * D];// weights transposed: [which][h][s][d]
__device__ __half g_xc[(size_t)T * D];         // x, fp16

// ---------------------------------------------------------------------------
__device__ __forceinline__ uint32_t smem_u32(const void* p) {
    uint32_t a;
    asm("{ .reg .u64 t; cvta.to.shared.u64 t, %1; cvt.u32.u64 %0, t; }" : "=r"(a) : "l"(p));
    return a;
}
__device__ __forceinline__ void ldmx4(uint32_t r[4], uint32_t a) {
    asm volatile("ldmatrix.sync.aligned.m8n8.x4.shared.b16 {%0,%1,%2,%3}, [%4];"
                 : "=r"(r[0]), "=r"(r[1]), "=r"(r[2]), "=r"(r[3]) : "r"(a));
}
__device__ __forceinline__ void ldmx4t(uint32_t r[4], uint32_t a) {
    asm volatile("ldmatrix.sync.aligned.m8n8.x4.trans.shared.b16 {%0,%1,%2,%3}, [%4];"
                 : "=r"(r[0]), "=r"(r[1]), "=r"(r[2]), "=r"(r[3]) : "r"(a));
}
__device__ __forceinline__ void mma16(float d[4], const uint32_t a[4],
                                      uint32_t b0, uint32_t b1) {
    asm volatile("mma.sync.aligned.m16n8k16.row.col.f32.f16.f16.f32 "
                 "{%0,%1,%2,%3}, {%4,%5,%6,%7}, {%8,%9}, {%0,%1,%2,%3};"
                 : "+f"(d[0]), "+f"(d[1]), "+f"(d[2]), "+f"(d[3])
                 : "r"(a[0]), "r"(a[1]), "r"(a[2]), "r"(a[3]), "r"(b0), "r"(b1));
}
__device__ __forceinline__ uint32_t packh2(float lo, float hi) {
    __half2 h = __floats2half2_rn(lo, hi);
    return *(uint32_t*)&h;
}
__device__ __forceinline__ uint32_t ex2h2(uint32_t h) {
    uint32_t r;
    asm("ex2.approx.f16x2 %0, %1;" : "=r"(r) : "r"(h));
    return r;
}
#define CPA16(dst, src) asm volatile("cp.async.cg.shared.global [%0], [%1], 16;" :: "r"(dst), "l"(src) : "memory")
#define CPC()  asm volatile("cp.async.commit_group;" ::: "memory")
#define CPW0() asm volatile("cp.async.wait_group 0;" ::: "memory")

// rows of 64 halfs (128 B = 8x16B units); XOR-swizzle -> conflict-free ldmatrix
__device__ __forceinline__ uint32_t swb(uint32_t row, uint32_t u) {
    return row * 128u + ((u ^ (row & 7u)) << 4);
}

// ---------------------------------------------------------------------------
__global__ __launch_bounds__(256) void xconv(const float* __restrict__ x) {
    int i = blockIdx.x * 256 + threadIdx.x;     // float4 index
    float4 v = ((const float4*)x)[i];
    __half2 a = __floats2half2_rn(v.x, v.y), b = __floats2half2_rn(v.z, v.w);
    *(__half2*)(g_xc + i * 4)     = a;
    *(__half2*)(g_xc + i * 4 + 2) = b;
}

__global__ void wtrans(const float* __restrict__ Wk, const float* __restrict__ Wq,
                       const float* __restrict__ Wv) {
    const int which = blockIdx.z / H, h = blockIdx.z % H;
    const float* W = ((which == 0) ? Wk : (which == 1) ? Wq : Wv) + (size_t)h * D * HS;
    const int d0 = blockIdx.x * 32, s0 = blockIdx.y * 32;
    __shared__ float t[32][33];
    const int tx = threadIdx.x, ty = threadIdx.y;
    #pragma unroll
    for (int i = 0; i < 4; i++)
        t[ty + i * 8][tx] = W[(size_t)(d0 + ty + i * 8) * HS + s0 + tx];
    __syncthreads();
    __half* o = g_Wt + ((size_t)(which * H + h) * HS + s0) * D + d0;
    #pragma unroll
    for (int i = 0; i < 4; i++)
        o[(size_t)(ty + i * 8) * D + tx] = __float2half_rn(t[tx][ty + i * 8]);
}

// ---------------------------------------------------------------------------
// Projection: Out[h][t][s] = sum_d xc[t][d] * Wt[wh][h][s][d]   (fp16 HMMA)
// M=128, N=64, K chunks of 64, 2-stage cp.async, one barrier per chunk.
// SMEM: A 2x(128x64 h), B 2x(64x64 h) = 49152 B.
// ---------------------------------------------------------------------------
__global__ __launch_bounds__(128, 3) void proj_tc() {
    extern __shared__ char smc[];
    const int tid = threadIdx.x, w = tid >> 5, l = tid & 31;
    const int mt = blockIdx.x, h = blockIdx.y, wh = blockIdx.z;
    const __half* A = g_xc + (size_t)mt * 128 * D;
    const __half* B = g_Wt + (size_t)(wh * H + h) * HS * D;
    const uint32_t sA = smem_u32(smc);            // 2 x 16384
    const uint32_t sB = sA + 2 * 16384;           // 2 x 8192

    auto stage = [&](int c, int st) {
        const __half* ap = A + c * 64;
        uint32_t da = sA + st * 16384;
        #pragma unroll
        for (int i = 0; i < 8; i++) {
            int id = tid + i * 128, r = id >> 3, u = id & 7;
            CPA16(da + swb(r, u), ap + (size_t)r * D + u * 8);
        }
        const __half* bp = B + c * 64;
        uint32_t db = sB + st * 8192;
        #pragma unroll
        for (int i = 0; i < 4; i++) {
            int id = tid + i * 128, r = id >> 3, u = id & 7;
            CPA16(db + swb(r, u), bp + (size_t)r * D + u * 8);
        }
    };
    stage(0, 0); CPC();

    float acc[2][8][4] = {};
    const int ar = ((l >> 3) & 1) * 8 + (l & 7);
    const int au = (l >> 4) & 1;
    const int kr = (l >> 4) * 8 + (l & 7);        // B-frag row pattern
    const int ku = (l >> 3) & 1;

    for (int c = 0; c < 16; c++) {
        const int st = c & 1;
        CPW0();
        __syncthreads();
        if (c + 1 < 16) { stage(c + 1, st ^ 1); CPC(); }
        const uint32_t abase = sA + st * 16384 + (w * 32) * 128;
        const uint32_t bbase = sB + st * 8192;
        #pragma unroll
        for (int kb = 0; kb < 4; kb++) {
            uint32_t qa0[4], qa1[4];
            ldmx4(qa0, abase + swb(ar,      2 * kb + au));
            ldmx4(qa1, abase + swb(16 + ar, 2 * kb + au));
            #pragma unroll
            for (int np = 0; np < 4; np++) {
                uint32_t q[4];
                ldmx4(q, bbase + swb(16 * np + kr, 2 * kb + ku));
                mma16(acc[0][2 * np],     qa0, q[0], q[1]);
                mma16(acc[0][2 * np + 1], qa0, q[2], q[3]);
                mma16(acc[1][2 * np],     qa1, q[0], q[1]);
                mma16(acc[1][2 * np + 1], qa1, q[2], q[3]);
            }
        }
    }

    __half* o = ((wh == 0) ? g_K : (wh == 1) ? g_Q : g_V) + (size_t)h * T * HS;
    #pragma unroll
    for (int mi = 0; mi < 2; mi++)
        #pragma unroll
        for (int ns = 0; ns < 8; ns++) {
            int s = ns * 8 + 2 * (l & 3);
            int t = mt * 128 + w * 32 + mi * 16 + (l >> 2);
            *(uint32_t*)(o + (size_t)t * HS + s)       = packh2(acc[mi][ns][0], acc[mi][ns][1]);
            *(uint32_t*)(o + (size_t)(t + 8) * HS + s) = packh2(acc[mi][ns][2], acc[mi][ns][3]);
        }
}

// ---------------------------------------------------------------------------
// Fused causal attention, fp16 HMMA. CTA = (q-tile pair, head), 128 threads.
// 64-row q-tiles; CTA processes {pair, 63-pair} -> uniform 65 kv-blocks/CTA.
// Softmax via ex2.approx.f16x2 (mask folded into FFMA addend; exp(masked)=0),
// row-sum l via all-ones-B mma accumulated in fp32 (no FADD chain, no shfl).
// SMEM 32 KB: K[2][64x64h] @0, V[2][64x64h] @16384. Q staged through K region.
// ---------------------------------------------------------------------------
__global__ __launch_bounds__(128, 4) void attn_tc(float* __restrict__ out) {
    extern __shared__ char smc[];
    const uint32_t sb = smem_u32(smc);
    const int tid = threadIdx.x, w = tid >> 5, l = tid & 31;
    const int pair = blockIdx.x, h = blockIdx.y;

    const __half* Qh = g_K + (size_t)h * T * HS;   // acts as queries
    const __half* Kp = g_Q + (size_t)h * T * HS;   // acts as keys
    const __half* Vp = g_V + (size_t)h * T * HS;

    const int ar = ((l >> 3) & 1) * 8 + (l & 7);
    const int au = (l >> 4) & 1;
    const int kr = (l >> 4) * 8 + (l & 7);        // K B-frag rows
    const int ku = (l >> 3) & 1;
    const int vr = ((l >> 3) & 1) * 8 + (l & 7);  // V trans-frag rows
    const int vu = (l >> 4) & 1;
    const int qd = l & 3, rlo = l >> 2;
    const float C = 0.18033688f;                  // 0.125 * log2(e)
    const uint32_t ONES = 0x3C003C00u;            // half2(1,1)

    auto stage = [&](int kbp, int stg) {
        const __half* kp = Kp + (size_t)kbp * 64 * HS;
        const uint32_t kd = sb + stg * 8192;
        #pragma unroll
        for (int i = 0; i < 4; i++) {
            int id = tid + i * 128, r = id >> 3, u = id & 7;
            CPA16(kd + swb(r, u), kp + (size_t)r * HS + u * 8);
        }
        const __half* vp = Vp + (size_t)kbp * 64 * HS;
        const uint32_t vd = sb + 16384 + stg * 8192;
        #pragma unroll
        for (int i = 0; i < 4; i++) {
            int id = tid + i * 128, r = id >> 3, u = id & 7;
            CPA16(vd + swb(r, u), vp + (size_t)r * HS + u * 8);
        }
    };

    #pragma unroll 1
    for (int tile = 0; tile < 2; tile++) {
        const int qb  = tile ? (63 - pair) : pair;
        const int nkb = qb + 1;
        const int row0 = qb * 64 + w * 16;

        // drain any in-flight prefetch from previous tile, then stage Q
        CPW0();
        __syncthreads();
        const __half* Qp = Qh + (size_t)qb * 64 * HS;
        #pragma unroll
        for (int i = 0; i < 4; i++) {
            int id = tid + i * 128, r = id >> 3, u = id & 7;
            CPA16(sb + swb(r, u), Qp + (size_t)r * HS + u * 8);
        }
        CPC(); CPW0();
        __syncthreads();
        uint32_t qa[4][4];
        #pragma unroll
        for (int kb2 = 0; kb2 < 4; kb2++)
            ldmx4(qa[kb2], sb + swb(w * 16 + ar, 2 * kb2 + au));
        __syncthreads();

        stage(0, 0); CPC();

        float oacc[8][4] = {};
        float lacc[4] = {};

        for (int kb = 0; kb < nkb; kb++) {
            const int st = kb & 1;
            CPW0();
            __syncthreads();
            const int kbp = (kb + 1 < nkb) ? kb + 1 : kb;
            stage(kbp, st ^ 1); CPC();

            const uint32_t kbase = sb + st * 8192;
            const uint32_t vbase = sb + 16384 + st * 8192;
            const int cb0 = kb * 64;

            // number of live 16-column blocks for this warp (1..4)
            int lim = ((row0 + 15 - cb0) >> 4) + 1;
            if (lim > 4) lim = 4;

            // --- S-mma for column block ntp into sacc ---
            auto smma = [&](int ntp, float sacc[2][4]) {
                sacc[0][0] = sacc[0][1] = sacc[0][2] = sacc[0][3] = 0.0f;
                sacc[1][0] = sacc[1][1] = sacc[1][2] = sacc[1][3] = 0.0f;
                #pragma unroll
                for (int kb2 = 0; kb2 < 4; kb2++) {
                    uint32_t q[4];
                    ldmx4(q, kbase + swb(16 * ntp + kr, 2 * kb2 + ku));
                    mma16(sacc[0], qa[kb2], q[0], q[1]);
                    mma16(sacc[1], qa[kb2], q[2], q[3]);
                }
            };
            // --- softmax (f16x2 ex2, mask via FFMA addend) + l-mma + O-mma ---
            auto proc = [&](int ntp, float sacc[2][4]) {
                const int cmin = cb0 + ntp * 16;
                const bool nomask = (cmin + 15) <= row0;
                uint32_t pa[4];
                #pragma unroll
                for (int ni = 0; ni < 2; ni++) {
                    float m0 = 0.0f, m1 = 0.0f, m2 = 0.0f, m3 = 0.0f;
                    if (!nomask) {
                        const int c0 = cmin + ni * 8 + 2 * qd;
                        const int r0 = row0 + rlo;
                        m0 = (c0     <= r0    ) ? 0.0f : -1e4f;
                        m1 = (c0 + 1 <= r0    ) ? 0.0f : -1e4f;
                        m2 = (c0     <= r0 + 8) ? 0.0f : -1e4f;
                        m3 = (c0 + 1 <= r0 + 8) ? 0.0f : -1e4f;
                    }
                    pa[2 * ni]     = ex2h2(packh2(fmaf(sacc[ni][0], C, m0),
                                                  fmaf(sacc[ni][1], C, m1)));
                    pa[2 * ni + 1] = ex2h2(packh2(fmaf(sacc[ni][2], C, m2),
                                                  fmaf(sacc[ni][3], C, m3)));
                }
                mma16(lacc, pa, ONES, ONES);    // lacc[0]=l(r), lacc[2]=l(r+8)
                #pragma unroll
                for (int jp = 0; jp < 4; jp++) {
                    uint32_t q[4];
                    ldmx4t(q, vbase + swb(16 * ntp + vr, 2 * jp + vu));
                    mma16(oacc[2 * jp],     pa, q[0], q[1]);
                    mma16(oacc[2 * jp + 1], pa, q[2], q[3]);
                }
            };

            // explicit depth-1 lookahead ladder (ping-pong sacc buffers)
            float sa[2][4], sbuf[2][4];
            smma(0, sa);
            if (lim > 1) {
                smma(1, sbuf);
                proc(0, sa);
                if (lim > 2) {
                    smma(2, sa);
                    proc(1, sbuf);
                    if (lim > 3) {
                        smma(3, sbuf);
                        proc(2, sa);
                        proc(3, sbuf);
                    } else {
                        proc(2, sa);
                    }
                } else {
                    proc(1, sbuf);
                }
            } else {
                proc(0, sa);
            }
        }

        // finalize tile: l already fully reduced by the ones-mma
        const float il0 = 1.0f / lacc[0];
        const float il1 = 1.0f / lacc[2];
        #pragma unroll
        for (int ns = 0; ns < 8; ns++) {
            int t0 = row0 + rlo;
            int c  = h * HS + ns * 8 + 2 * qd;
            *(float2*)(out + (size_t)t0 * (H * HS) + c) =
                make_float2(oacc[ns][0] * il0, oacc[ns][1] * il0);
            *(float2*)(out + (size_t)(t0 + 8) * (H * HS) + c) =
                make_float2(oacc[ns][2] * il1, oacc[ns][3] * il1);
        }
    }
}

// ---------------------------------------------------------------------------
extern "C" void kernel_launch(void* const* d_in, const int* in_sizes, int n_in,
                              void* d_out, int out_size) {
    const float* x  = (const float*)d_in[0];
    const float* Wk = (const float*)d_in[1];
    const float* Wq = (const float*)d_in[2];
    const float* Wv = (const float*)d_in[3];
    float* out = (float*)d_out;

    cudaFuncSetAttribute(proj_tc, cudaFuncAttributeMaxDynamicSharedMemorySize, 49152);
    cudaFuncSetAttribute(attn_tc, cudaFuncAttributeMaxDynamicSharedMemorySize, 32768);

    xconv<<<T * D / 4 / 256, 256>>>(x);
    wtrans<<<dim3(D / 32, HS / 32, 3 * H), dim3(32, 8)>>>(Wk, Wq, Wv);
    proj_tc<<<dim3(T / 128, H, 3), 128, 49152>>>();
    attn_tc<<<dim3(T / 128 * 2 / 2, H), 128, 32768>>>(out);
}